// round 5
// baseline (speedup 1.0000x reference)
#include <cuda_runtime.h>
#include <cuda_bf16.h>
#include <stdint.h>

// NearestMean: out[i] = labels[ sum_j (x[i] >= thresholds[j]) ]
// Output written as FLOAT32 (theory: harness __output__ dtype is float32,
// from the original torch module's full_like/float semantics).

// Decode one 4-byte word that may hold an int32 label or a float32 label.
__device__ __forceinline__ float decode_label_word(uint32_t w) {
    if (w == 0u) return 0.0f;
    float f = __uint_as_float(w);
    float af = fabsf(f);
    // Plausible float32 label: finite, |v| in [1e-6, 1e6].
    uint32_t exp = (w >> 23) & 0xFFu;
    if (exp != 0xFFu && af >= 1e-6f && af <= 1e6f) return f;
    // Otherwise treat the bits as a signed int32 label.
    return (float)(int)w;
}

// Sniff thresholds: prefer float32 read; fall back to float64 if implausible.
__device__ __forceinline__ void load_thresholds(const void* p, float& t0, float& t1, float& t2) {
    const float* pf = (const float*)p;
    float a = pf[0], b = pf[1], c = pf[2];
    bool ok = isfinite(a) && isfinite(b) && isfinite(c) &&
              (a < b) && (b < c) &&
              fabsf(a) < 1e8f && fabsf(c) < 1e8f;
    if (ok) { t0 = a; t1 = b; t2 = c; return; }
    const double* pd = (const double*)p;
    t0 = (float)pd[0]; t1 = (float)pd[1]; t2 = (float)pd[2];
}

// Sniff labels: int32 / float32 / int64 layouts.
__device__ __forceinline__ void load_labels(const void* p, float& l0, float& l1, float& l2, float& l3) {
    const uint32_t* lr = (const uint32_t*)p;
    uint32_t w0 = lr[0], w1 = lr[1], w2 = lr[2], w3 = lr[3];
    // int64 signature: odd words (high halves) zero while some later low half nonzero.
    if (w1 == 0u && w3 == 0u && (w2 != 0u || w0 != 0u)) {
        const uint32_t* l8 = lr;   // safe: under this hypothesis buffer is 32B
        l0 = (float)(int)l8[0];
        l1 = (float)(int)l8[2];
        l2 = (float)(int)l8[4];
        l3 = (float)(int)l8[6];
        return;
    }
    l0 = decode_label_word(w0);
    l1 = decode_label_word(w1);
    l2 = decode_label_word(w2);
    l3 = decode_label_word(w3);
}

__global__ __launch_bounds__(256) void nearest_mean_vec4_f32(
    const float4* __restrict__ x4,
    const void* __restrict__ thrRaw,
    const void* __restrict__ labsRaw,
    float4* __restrict__ out4,
    long long n4)
{
    long long i = (long long)blockIdx.x * blockDim.x + threadIdx.x;
    if (i >= n4) return;

    float t0, t1, t2;
    load_thresholds(thrRaw, t0, t1, t2);
    float l0, l1, l2, l3;
    load_labels(labsRaw, l0, l1, l2, l3);

    float4 v = x4[i];

    int i0 = (v.x >= t0) + (v.x >= t1) + (v.x >= t2);
    int i1 = (v.y >= t0) + (v.y >= t1) + (v.y >= t2);
    int i2 = (v.z >= t0) + (v.z >= t1) + (v.z >= t2);
    int i3 = (v.w >= t0) + (v.w >= t1) + (v.w >= t2);

    float4 r;
    r.x = (i0 == 0) ? l0 : (i0 == 1) ? l1 : (i0 == 2) ? l2 : l3;
    r.y = (i1 == 0) ? l0 : (i1 == 1) ? l1 : (i1 == 2) ? l2 : l3;
    r.z = (i2 == 0) ? l0 : (i2 == 1) ? l1 : (i2 == 2) ? l2 : l3;
    r.w = (i3 == 0) ? l0 : (i3 == 1) ? l1 : (i3 == 2) ? l2 : l3;
    out4[i] = r;
}

__global__ __launch_bounds__(256) void nearest_mean_scalar_f32(
    const float* __restrict__ x,
    const void* __restrict__ thrRaw,
    const void* __restrict__ labsRaw,
    float* __restrict__ out,
    long long n)
{
    long long i = (long long)blockIdx.x * blockDim.x + threadIdx.x;
    if (i >= n) return;

    float t0, t1, t2;
    load_thresholds(thrRaw, t0, t1, t2);
    float l0, l1, l2, l3;
    load_labels(labsRaw, l0, l1, l2, l3);

    float v = x[i];
    int idx = (v >= t0) + (v >= t1) + (v >= t2);
    out[i] = (idx == 0) ? l0 : (idx == 1) ? l1 : (idx == 2) ? l2 : l3;
}

extern "C" void kernel_launch(void* const* d_in, const int* in_sizes, int n_in,
                              void* d_out, int out_size)
{
    // Identify inputs by element count: X = largest; of the two small arrays,
    // thresholds is the smaller (K-1), labels the larger (K).
    int xi = 0;
    for (int k = 1; k < n_in; k++)
        if (in_sizes[k] > in_sizes[xi]) xi = k;

    int ti = -1, li = -1;
    for (int k = 0; k < n_in; k++) {
        if (k == xi) continue;
        if (ti < 0) { ti = k; continue; }
        li = k;
    }
    if (ti >= 0 && li >= 0 && in_sizes[ti] > in_sizes[li]) {
        int tmp = ti; ti = li; li = tmp;
    }
    if (li < 0) li = ti;

    const float* X   = (const float*)d_in[xi];
    const void* thr  = d_in[ti];
    const void* labs = d_in[li];
    float* out = (float*)d_out;

    long long n = (long long)in_sizes[xi];
    const int threads = 256;

    bool aligned = (((uintptr_t)X & 15u) == 0) && (((uintptr_t)out & 15u) == 0);

    if (aligned && (n % 4 == 0)) {
        long long n4 = n / 4;
        long long blocks = (n4 + threads - 1) / threads;
        nearest_mean_vec4_f32<<<(unsigned)blocks, threads>>>(
            (const float4*)X, thr, labs, (float4*)out, n4);
    } else {
        long long blocks = (n + threads - 1) / threads;
        nearest_mean_scalar_f32<<<(unsigned)blocks, threads>>>(X, thr, labs, out, n);
    }
}

// round 7
// speedup vs baseline: 1.3572x; 1.3572x over previous
#include <cuda_runtime.h>
#include <cuda_bf16.h>
#include <stdint.h>

// NearestMean: out[i] = labels[ sum_j (x[i] >= thresholds[j]) ], float32 output.
// R5 passed (229.5us) but was half issue-bound (alu 50.8%). This version hoists
// all dtype-sniffing into a 1-thread prologue and minimizes hot-path ALU.

__device__ float g_params[7];   // t0,t1,t2,l0,l1,l2,l3

// ---------- prologue: decode thresholds/labels once ----------
__device__ __forceinline__ float decode_label_word(uint32_t w) {
    if (w == 0u) return 0.0f;
    float f = __uint_as_float(w);
    float af = fabsf(f);
    uint32_t exp = (w >> 23) & 0xFFu;
    if (exp != 0xFFu && af >= 1e-6f && af <= 1e6f) return f;   // plausible float32
    return (float)(int)w;                                       // else int32 bits
}

__global__ void nm_decode_params(const void* __restrict__ thrRaw,
                                 const void* __restrict__ labsRaw)
{
    // thresholds: float32 preferred, float64 fallback
    const float* pf = (const float*)thrRaw;
    float a = pf[0], b = pf[1], c = pf[2];
    bool ok = isfinite(a) && isfinite(b) && isfinite(c) &&
              (a < b) && (b < c) && fabsf(a) < 1e8f && fabsf(c) < 1e8f;
    if (!ok) {
        const double* pd = (const double*)thrRaw;
        a = (float)pd[0]; b = (float)pd[1]; c = (float)pd[2];
    }
    g_params[0] = a; g_params[1] = b; g_params[2] = c;

    // labels: int32 / float32 / int64 layouts
    const uint32_t* lr = (const uint32_t*)labsRaw;
    uint32_t w0 = lr[0], w1 = lr[1], w2 = lr[2], w3 = lr[3];
    float l0, l1, l2, l3;
    if (w1 == 0u && w3 == 0u && (w2 != 0u || w0 != 0u)) {      // int64 signature
        l0 = (float)(int)lr[0];
        l1 = (float)(int)lr[2];
        l2 = (float)(int)lr[4];
        l3 = (float)(int)lr[6];
    } else {
        l0 = decode_label_word(w0);
        l1 = decode_label_word(w1);
        l2 = decode_label_word(w2);
        l3 = decode_label_word(w3);
    }
    g_params[3] = l0; g_params[4] = l1; g_params[5] = l2; g_params[6] = l3;
}

// ---------- hot path ----------
__device__ __forceinline__ float bucket(float v, float t0, float t1, float t2,
                                        float l0, float l1, float l2, float l3)
{
    // 3 FSETP + 3 FSEL, no integer math
    float r = (v >= t2) ? l3 : l2;
    r = (v >= t1) ? r : l1;
    r = (v >= t0) ? r : l0;
    return r;
}

#define NM_ILP 4

__global__ __launch_bounds__(256) void nm_vec4(
    const float4* __restrict__ x4,
    float4* __restrict__ out4,
    long long n4)
{
    const float t0 = g_params[0], t1 = g_params[1], t2 = g_params[2];
    const float l0 = g_params[3], l1 = g_params[4], l2 = g_params[5], l3 = g_params[6];

    long long base = (long long)blockIdx.x * (256 * NM_ILP) + threadIdx.x;

    float4 v[NM_ILP];
    bool ok[NM_ILP];
    #pragma unroll
    for (int k = 0; k < NM_ILP; k++) {
        long long i = base + (long long)k * 256;
        ok[k] = (i < n4);
        if (ok[k]) v[k] = x4[i];      // front-batched LDG.128s -> MLP=4
    }

    #pragma unroll
    for (int k = 0; k < NM_ILP; k++) {
        if (ok[k]) {
            long long i = base + (long long)k * 256;
            float4 r;
            r.x = bucket(v[k].x, t0, t1, t2, l0, l1, l2, l3);
            r.y = bucket(v[k].y, t0, t1, t2, l0, l1, l2, l3);
            r.z = bucket(v[k].z, t0, t1, t2, l0, l1, l2, l3);
            r.w = bucket(v[k].w, t0, t1, t2, l0, l1, l2, l3);
            out4[i] = r;
        }
    }
}

__global__ __launch_bounds__(256) void nm_scalar(
    const float* __restrict__ x,
    float* __restrict__ out,
    long long n)
{
    const float t0 = g_params[0], t1 = g_params[1], t2 = g_params[2];
    const float l0 = g_params[3], l1 = g_params[4], l2 = g_params[5], l3 = g_params[6];

    long long i = (long long)blockIdx.x * blockDim.x + threadIdx.x;
    if (i >= n) return;
    out[i] = bucket(x[i], t0, t1, t2, l0, l1, l2, l3);
}

extern "C" void kernel_launch(void* const* d_in, const int* in_sizes, int n_in,
                              void* d_out, int out_size)
{
    // Identify inputs by element count: X = largest; thresholds = smaller small
    // array (K-1); labels = larger small array (K).
    int xi = 0;
    for (int k = 1; k < n_in; k++)
        if (in_sizes[k] > in_sizes[xi]) xi = k;

    int ti = -1, li = -1;
    for (int k = 0; k < n_in; k++) {
        if (k == xi) continue;
        if (ti < 0) { ti = k; continue; }
        li = k;
    }
    if (ti >= 0 && li >= 0 && in_sizes[ti] > in_sizes[li]) {
        int tmp = ti; ti = li; li = tmp;
    }
    if (li < 0) li = ti;

    const float* X = (const float*)d_in[xi];
    float* out = (float*)d_out;
    long long n = (long long)in_sizes[xi];

    nm_decode_params<<<1, 1>>>(d_in[ti], d_in[li]);

    bool aligned = (((uintptr_t)X & 15u) == 0) && (((uintptr_t)out & 15u) == 0);

    if (aligned && (n % 4 == 0)) {
        long long n4 = n / 4;
        long long blocks = (n4 + 256LL * NM_ILP - 1) / (256LL * NM_ILP);
        nm_vec4<<<(unsigned)blocks, 256>>>((const float4*)X, (float4*)out, n4);
    } else {
        long long blocks = (n + 255) / 256;
        nm_scalar<<<(unsigned)blocks, 256>>>(X, out, n);
    }
}

// round 8
// speedup vs baseline: 1.3686x; 1.0084x over previous
#include <cuda_runtime.h>
#include <cuda_bf16.h>
#include <stdint.h>

// NearestMean: out[i] = labels[ sum_j (x[i] >= thresholds[j]) ], float32 output.
// R7: 169.1us = 159.1us kernel (86.3% DRAM, at roofline) + ~10us serialized
// 1-thread decode prologue. This round fuses the decode into the main kernel
// (per-thread, ~40 instrs, negligible at ILP=4's 69.8k warps) and drops the
// prologue launch entirely.

// ---------- param decode (uniform, cheap at ILP=4 thread counts) ----------
__device__ __forceinline__ float decode_label_word(uint32_t w) {
    if (w == 0u) return 0.0f;
    float f = __uint_as_float(w);
    float af = fabsf(f);
    uint32_t exp = (w >> 23) & 0xFFu;
    if (exp != 0xFFu && af >= 1e-6f && af <= 1e6f) return f;   // plausible float32
    return (float)(int)w;                                       // else int32 bits
}

__device__ __forceinline__ void decode_params(
    const void* __restrict__ thrRaw, const void* __restrict__ labsRaw,
    float& t0, float& t1, float& t2,
    float& l0, float& l1, float& l2, float& l3)
{
    // thresholds: float32 preferred, float64 fallback
    const float* pf = (const float*)thrRaw;
    float a = pf[0], b = pf[1], c = pf[2];
    bool ok = isfinite(a) && isfinite(b) && isfinite(c) &&
              (a < b) && (b < c) && fabsf(a) < 1e8f && fabsf(c) < 1e8f;
    if (!ok) {
        const double* pd = (const double*)thrRaw;
        a = (float)pd[0]; b = (float)pd[1]; c = (float)pd[2];
    }
    t0 = a; t1 = b; t2 = c;

    // labels: int32 / float32 / int64 layouts
    const uint32_t* lr = (const uint32_t*)labsRaw;
    uint32_t w0 = lr[0], w1 = lr[1], w2 = lr[2], w3 = lr[3];
    if (w1 == 0u && w3 == 0u && (w2 != 0u || w0 != 0u)) {      // int64 signature
        l0 = (float)(int)lr[0];
        l1 = (float)(int)lr[2];
        l2 = (float)(int)lr[4];
        l3 = (float)(int)lr[6];
    } else {
        l0 = decode_label_word(w0);
        l1 = decode_label_word(w1);
        l2 = decode_label_word(w2);
        l3 = decode_label_word(w3);
    }
}

// ---------- hot path ----------
__device__ __forceinline__ float bucket(float v, float t0, float t1, float t2,
                                        float l0, float l1, float l2, float l3)
{
    float r = (v >= t2) ? l3 : l2;
    r = (v >= t1) ? r : l1;
    r = (v >= t0) ? r : l0;
    return r;
}

#define NM_ILP 4

__global__ __launch_bounds__(256) void nm_vec4(
    const float4* __restrict__ x4,
    const void* __restrict__ thrRaw,
    const void* __restrict__ labsRaw,
    float4* __restrict__ out4,
    long long n4)
{
    float t0, t1, t2, l0, l1, l2, l3;
    decode_params(thrRaw, labsRaw, t0, t1, t2, l0, l1, l2, l3);

    long long base = (long long)blockIdx.x * (256 * NM_ILP) + threadIdx.x;

    float4 v[NM_ILP];
    bool ok[NM_ILP];
    #pragma unroll
    for (int k = 0; k < NM_ILP; k++) {
        long long i = base + (long long)k * 256;
        ok[k] = (i < n4);
        if (ok[k]) v[k] = x4[i];      // front-batched LDG.128s -> MLP=4
    }

    #pragma unroll
    for (int k = 0; k < NM_ILP; k++) {
        if (ok[k]) {
            long long i = base + (long long)k * 256;
            float4 r;
            r.x = bucket(v[k].x, t0, t1, t2, l0, l1, l2, l3);
            r.y = bucket(v[k].y, t0, t1, t2, l0, l1, l2, l3);
            r.z = bucket(v[k].z, t0, t1, t2, l0, l1, l2, l3);
            r.w = bucket(v[k].w, t0, t1, t2, l0, l1, l2, l3);
            out4[i] = r;
        }
    }
}

__global__ __launch_bounds__(256) void nm_scalar(
    const float* __restrict__ x,
    const void* __restrict__ thrRaw,
    const void* __restrict__ labsRaw,
    float* __restrict__ out,
    long long n)
{
    float t0, t1, t2, l0, l1, l2, l3;
    decode_params(thrRaw, labsRaw, t0, t1, t2, l0, l1, l2, l3);

    long long i = (long long)blockIdx.x * blockDim.x + threadIdx.x;
    if (i >= n) return;
    out[i] = bucket(x[i], t0, t1, t2, l0, l1, l2, l3);
}

extern "C" void kernel_launch(void* const* d_in, const int* in_sizes, int n_in,
                              void* d_out, int out_size)
{
    // Identify inputs by element count: X = largest; thresholds = smaller small
    // array (K-1); labels = larger small array (K).
    int xi = 0;
    for (int k = 1; k < n_in; k++)
        if (in_sizes[k] > in_sizes[xi]) xi = k;

    int ti = -1, li = -1;
    for (int k = 0; k < n_in; k++) {
        if (k == xi) continue;
        if (ti < 0) { ti = k; continue; }
        li = k;
    }
    if (ti >= 0 && li >= 0 && in_sizes[ti] > in_sizes[li]) {
        int tmp = ti; ti = li; li = tmp;
    }
    if (li < 0) li = ti;

    const float* X = (const float*)d_in[xi];
    float* out = (float*)d_out;
    long long n = (long long)in_sizes[xi];

    bool aligned = (((uintptr_t)X & 15u) == 0) && (((uintptr_t)out & 15u) == 0);

    if (aligned && (n % 4 == 0)) {
        long long n4 = n / 4;
        long long blocks = (n4 + 256LL * NM_ILP - 1) / (256LL * NM_ILP);
        nm_vec4<<<(unsigned)blocks, 256>>>(
            (const float4*)X, d_in[ti], d_in[li], (float4*)out, n4);
    } else {
        long long blocks = (n + 255) / 256;
        nm_scalar<<<(unsigned)blocks, 256>>>(X, d_in[ti], d_in[li], out, n);
    }
}

// round 9
// speedup vs baseline: 1.3794x; 1.0079x over previous
#include <cuda_runtime.h>
#include <cuda_bf16.h>
#include <stdint.h>

// NearestMean: out[i] = labels[ sum_j (x[i] >= thresholds[j]) ], float32 output.
// R8: 167.7us e2e = 160.3us kernel (85.7% DRAM) + ~7us fixed harness overhead.
// R9: streaming cache hints (__ldcs/__stcs), exact-tile no-bounds-check variant,
// 32-bit indexing. Target: squeeze kernel toward the ~7.2TB/s mixed r/w ceiling.

// ---------- param decode (uniform, negligible at ILP=4 thread counts) ----------
__device__ __forceinline__ float decode_label_word(uint32_t w) {
    if (w == 0u) return 0.0f;
    float f = __uint_as_float(w);
    float af = fabsf(f);
    uint32_t exp = (w >> 23) & 0xFFu;
    if (exp != 0xFFu && af >= 1e-6f && af <= 1e6f) return f;   // plausible float32
    return (float)(int)w;                                       // else int32 bits
}

__device__ __forceinline__ void decode_params(
    const void* __restrict__ thrRaw, const void* __restrict__ labsRaw,
    float& t0, float& t1, float& t2,
    float& l0, float& l1, float& l2, float& l3)
{
    const float* pf = (const float*)thrRaw;
    float a = pf[0], b = pf[1], c = pf[2];
    bool ok = isfinite(a) && isfinite(b) && isfinite(c) &&
              (a < b) && (b < c) && fabsf(a) < 1e8f && fabsf(c) < 1e8f;
    if (!ok) {
        const double* pd = (const double*)thrRaw;
        a = (float)pd[0]; b = (float)pd[1]; c = (float)pd[2];
    }
    t0 = a; t1 = b; t2 = c;

    const uint32_t* lr = (const uint32_t*)labsRaw;
    uint32_t w0 = lr[0], w1 = lr[1], w2 = lr[2], w3 = lr[3];
    if (w1 == 0u && w3 == 0u && (w2 != 0u || w0 != 0u)) {      // int64 signature
        l0 = (float)(int)lr[0];
        l1 = (float)(int)lr[2];
        l2 = (float)(int)lr[4];
        l3 = (float)(int)lr[6];
    } else {
        l0 = decode_label_word(w0);
        l1 = decode_label_word(w1);
        l2 = decode_label_word(w2);
        l3 = decode_label_word(w3);
    }
}

// ---------- hot path ----------
__device__ __forceinline__ float bucket(float v, float t0, float t1, float t2,
                                        float l0, float l1, float l2, float l3)
{
    float r = (v >= t2) ? l3 : l2;
    r = (v >= t1) ? r : l1;
    r = (v >= t0) ? r : l0;
    return r;
}

#define NM_ILP 4

// Exact-tile variant: grid*256*NM_ILP == n4. No bounds checks, 32-bit indexing,
// streaming loads/stores (single-touch data -> evict-first).
__global__ __launch_bounds__(256) void nm_vec4_exact(
    const float4* __restrict__ x4,
    const void* __restrict__ thrRaw,
    const void* __restrict__ labsRaw,
    float4* __restrict__ out4)
{
    float t0, t1, t2, l0, l1, l2, l3;
    decode_params(thrRaw, labsRaw, t0, t1, t2, l0, l1, l2, l3);

    unsigned base = blockIdx.x * (256u * NM_ILP) + threadIdx.x;

    float4 v[NM_ILP];
    #pragma unroll
    for (int k = 0; k < NM_ILP; k++)
        v[k] = __ldcs(&x4[base + (unsigned)k * 256u]);   // front-batched, MLP=4

    #pragma unroll
    for (int k = 0; k < NM_ILP; k++) {
        float4 r;
        r.x = bucket(v[k].x, t0, t1, t2, l0, l1, l2, l3);
        r.y = bucket(v[k].y, t0, t1, t2, l0, l1, l2, l3);
        r.z = bucket(v[k].z, t0, t1, t2, l0, l1, l2, l3);
        r.w = bucket(v[k].w, t0, t1, t2, l0, l1, l2, l3);
        __stcs(&out4[base + (unsigned)k * 256u], r);
    }
}

// General variant with bounds checks (fallback for non-divisible n4).
__global__ __launch_bounds__(256) void nm_vec4(
    const float4* __restrict__ x4,
    const void* __restrict__ thrRaw,
    const void* __restrict__ labsRaw,
    float4* __restrict__ out4,
    long long n4)
{
    float t0, t1, t2, l0, l1, l2, l3;
    decode_params(thrRaw, labsRaw, t0, t1, t2, l0, l1, l2, l3);

    long long base = (long long)blockIdx.x * (256 * NM_ILP) + threadIdx.x;

    float4 v[NM_ILP];
    bool ok[NM_ILP];
    #pragma unroll
    for (int k = 0; k < NM_ILP; k++) {
        long long i = base + (long long)k * 256;
        ok[k] = (i < n4);
        if (ok[k]) v[k] = __ldcs(&x4[i]);
    }

    #pragma unroll
    for (int k = 0; k < NM_ILP; k++) {
        if (ok[k]) {
            long long i = base + (long long)k * 256;
            float4 r;
            r.x = bucket(v[k].x, t0, t1, t2, l0, l1, l2, l3);
            r.y = bucket(v[k].y, t0, t1, t2, l0, l1, l2, l3);
            r.z = bucket(v[k].z, t0, t1, t2, l0, l1, l2, l3);
            r.w = bucket(v[k].w, t0, t1, t2, l0, l1, l2, l3);
            __stcs(&out4[i], r);
        }
    }
}

__global__ __launch_bounds__(256) void nm_scalar(
    const float* __restrict__ x,
    const void* __restrict__ thrRaw,
    const void* __restrict__ labsRaw,
    float* __restrict__ out,
    long long n)
{
    float t0, t1, t2, l0, l1, l2, l3;
    decode_params(thrRaw, labsRaw, t0, t1, t2, l0, l1, l2, l3);

    long long i = (long long)blockIdx.x * blockDim.x + threadIdx.x;
    if (i >= n) return;
    out[i] = bucket(x[i], t0, t1, t2, l0, l1, l2, l3);
}

extern "C" void kernel_launch(void* const* d_in, const int* in_sizes, int n_in,
                              void* d_out, int out_size)
{
    // Identify inputs by element count: X = largest; thresholds = smaller small
    // array (K-1); labels = larger small array (K).
    int xi = 0;
    for (int k = 1; k < n_in; k++)
        if (in_sizes[k] > in_sizes[xi]) xi = k;

    int ti = -1, li = -1;
    for (int k = 0; k < n_in; k++) {
        if (k == xi) continue;
        if (ti < 0) { ti = k; continue; }
        li = k;
    }
    if (ti >= 0 && li >= 0 && in_sizes[ti] > in_sizes[li]) {
        int tmp = ti; ti = li; li = tmp;
    }
    if (li < 0) li = ti;

    const float* X = (const float*)d_in[xi];
    float* out = (float*)d_out;
    long long n = (long long)in_sizes[xi];

    bool aligned = (((uintptr_t)X & 15u) == 0) && (((uintptr_t)out & 15u) == 0);

    if (aligned && (n % 4 == 0)) {
        long long n4 = n / 4;
        const long long tile = 256LL * NM_ILP;
        if ((n4 % tile) == 0 && (n4 / tile) <= 0x7FFFFFFFLL) {
            unsigned blocks = (unsigned)(n4 / tile);
            nm_vec4_exact<<<blocks, 256>>>(
                (const float4*)X, d_in[ti], d_in[li], (float4*)out);
        } else {
            long long blocks = (n4 + tile - 1) / tile;
            nm_vec4<<<(unsigned)blocks, 256>>>(
                (const float4*)X, d_in[ti], d_in[li], (float4*)out, n4);
        }
    } else {
        long long blocks = (n + 255) / 256;
        nm_scalar<<<(unsigned)blocks, 256>>>(X, d_in[ti], d_in[li], out, n);
    }
}